// round 2
// baseline (speedup 1.0000x reference)
#include <cuda_runtime.h>
#include <math.h>

#define BATCH 4
#define HEADS 8
#define BH 32
#define NSEQ 4096
#define DDIM 64
#define MDIM 266
#define MPAD 272      // 68 float4 columns
#define ECOLS 65      // 64 v-cols + 1 ones-col (k_mean)
#define EPAD 68
#define PSTR 68       // padded floats per 64-float row in smem (17 float4)
#define NORMALIZER 0.3535533905932738f   // 64^-0.25
#define DIAGC 0.0625f                    // 0.5 * 64^-0.5
#define KEPS 1e-4f
#define RATIO 0.06131393835f             // 266^-0.5

// ---------------- scratch (static device globals; no allocation) ----------
__device__ unsigned int g_stab_bits;                 // encoded global max of k_dash
__device__ float g_C[BH * MDIM * ECOLS];             // [bh][m][e] context + k_mean

// ordered-uint encoding for float atomicMax (monotonic, handles negatives)
__device__ __forceinline__ unsigned int fenc(float f) {
    unsigned int b = __float_as_uint(f);
    return (b & 0x80000000u) ? ~b : (b | 0x80000000u);
}
__device__ __forceinline__ float fdec(unsigned int u) {
    return (u & 0x80000000u) ? __uint_as_float(u & 0x7FFFFFFFu) : __uint_as_float(~u);
}

__global__ void init_kernel() {
    int i = blockIdx.x * blockDim.x + threadIdx.x;
    if (i == 0) g_stab_bits = 0u;
    int stride = gridDim.x * blockDim.x;
    for (int idx = i; idx < BH * MDIM * ECOLS; idx += stride) g_C[idx] = 0.0f;
}

// load projection [266][64] -> smem padded [266][68]
__device__ __forceinline__ void load_proj(float* ps, const float* __restrict__ proj, int tid) {
    const float4* p4 = (const float4*)proj;
    float4* ps4 = (float4*)ps;
    for (int i = tid; i < MDIM * 16; i += 256) {
        int m = i >> 4, d4 = i & 15;
        ps4[m * 17 + d4] = p4[i];
    }
}

// load a 32x64 fp32 tile -> smem padded [32][68]
__device__ __forceinline__ void load_tile64(float* ts, const float* __restrict__ src, int tid) {
    const float4* s4 = (const float4*)src;
    float4* t4 = (float4*)ts;
    for (int i = tid; i < 32 * 16; i += 256) {
        int r = i >> 4, d4 = i & 15;
        t4[r * 17 + d4] = s4[i];
    }
}

// =======================================================================
// Kernel A: global max over k_dash = NORMALIZER * (K @ P^T)
// grid: 32 bh * 32 chunks of 128 rows = 1024 blocks, 256 threads
// =======================================================================
__global__ void __launch_bounds__(256) kmax_kernel(const float* __restrict__ kk,
                                                   const float* __restrict__ proj) {
    extern __shared__ float sm[];
    float* ps = sm;                    // 266*68
    float* ks = ps + MDIM * PSTR;      // 32*68
    int tid = threadIdx.x;
    load_proj(ps, proj, tid);

    int bh = blockIdx.x >> 5;
    int row0 = (blockIdx.x & 31) * 128;
    const float* kbase = kk + ((size_t)bh * NSEQ + row0) * DDIM;

    int tx = tid & 63, ty = tid >> 6;
    const float4* ps4 = (const float4*)ps;
    const float4* ks4 = (const float4*)ks;
    float maxv = -INFINITY;

    for (int s = 0; s < 4; s++) {
        __syncthreads();
        load_tile64(ks, kbase + s * 32 * DDIM, tid);
        __syncthreads();
        for (int stripe = 0; stripe < 5; stripe++) {
            int m = stripe * 64 + tx;
            if (m < MDIM) {
                float acc[8];
#pragma unroll
                for (int r = 0; r < 8; r++) acc[r] = 0.f;
                const float4* pm = ps4 + m * 17;
#pragma unroll
                for (int d4 = 0; d4 < 16; d4++) {
                    float4 p = pm[d4];
#pragma unroll
                    for (int r = 0; r < 8; r++) {
                        float4 kv = ks4[(ty * 8 + r) * 17 + d4];
                        acc[r] = fmaf(p.x, kv.x, acc[r]);
                        acc[r] = fmaf(p.y, kv.y, acc[r]);
                        acc[r] = fmaf(p.z, kv.z, acc[r]);
                        acc[r] = fmaf(p.w, kv.w, acc[r]);
                    }
                }
#pragma unroll
                for (int r = 0; r < 8; r++) maxv = fmaxf(maxv, acc[r]);
            }
        }
    }
    __shared__ unsigned int red;
    if (tid == 0) red = 0u;
    __syncthreads();
    atomicMax(&red, fenc(NORMALIZER * maxv));
    __syncthreads();
    if (tid == 0) atomicMax(&g_stab_bits, red);
}

// =======================================================================
// Kernel B: context. Recompute kp and accumulate C[m][e] = sum_n kp/L * [V|1]
// grid: 32 bh * 8 chunks of 512 rows = 256 blocks, 256 threads
// =======================================================================
__global__ void __launch_bounds__(256) context_kernel(const float* __restrict__ kk,
                                                      const float* __restrict__ vv,
                                                      const float* __restrict__ proj) {
    extern __shared__ float sm[];
    float* ps   = sm;                        // 266*68 = 18088
    float* Cl   = ps + MDIM * PSTR;          // 272*68 = 18496
    float* kp   = Cl + MPAD * EPAD;          // 32*272 =  8704
    float* ks   = kp + 32 * MPAD;            // 32*68  =  2176
    float* vs   = ks + 32 * PSTR;            // 32*68  =  2176
    float* diag = vs + 32 * PSTR;            // 32

    int tid = threadIdx.x;
    load_proj(ps, proj, tid);
    for (int i = tid; i < MPAD * EPAD; i += 256) Cl[i] = 0.f;

    int bh = blockIdx.x >> 3;
    int row0 = (blockIdx.x & 7) * 512;
    const float* kbase = kk + ((size_t)bh * NSEQ + row0) * DDIM;
    const float* vbase = vv + ((size_t)bh * NSEQ + row0) * DDIM;
    const float stab = fdec(g_stab_bits);
    const float c1 = RATIO * (1.0f / (float)NSEQ);   // ratio / L

    int tx = tid & 63, ty = tid >> 6;
    const float4* ps4 = (const float4*)ps;
    const float4* ks4 = (const float4*)ks;
    float4* Cl4 = (float4*)Cl;
    const float4* kp4 = (const float4*)kp;
    const float4* vs4 = (const float4*)vs;

    for (int s = 0; s < 16; s++) {
        __syncthreads();
        load_tile64(ks, kbase + s * 32 * DDIM, tid);
        load_tile64(vs, vbase + s * 32 * DDIM, tid);
        __syncthreads();
        if (tid < 32) {
            float ssum = 0.f;
#pragma unroll
            for (int d4 = 0; d4 < 16; d4++) {
                float4 kv2 = ks4[tid * 17 + d4];
                ssum += kv2.x * kv2.x + kv2.y * kv2.y + kv2.z * kv2.z + kv2.w * kv2.w;
            }
            diag[tid] = DIAGC * ssum;
            vs[tid * PSTR + 64] = 1.0f;   // ones column -> k_mean
            vs[tid * PSTR + 65] = 0.f;
            vs[tid * PSTR + 66] = 0.f;
            vs[tid * PSTR + 67] = 0.f;
        }
        __syncthreads();

        // phase 1: kp rows for this 32-row subchunk
        for (int stripe = 0; stripe < 5; stripe++) {
            int m = stripe * 64 + tx;
            if (m < MPAD) {
                float acc[8];
#pragma unroll
                for (int r = 0; r < 8; r++) acc[r] = 0.f;
                if (m < MDIM) {
                    const float4* pm = ps4 + m * 17;
#pragma unroll
                    for (int d4 = 0; d4 < 16; d4++) {
                        float4 p = pm[d4];
#pragma unroll
                        for (int r = 0; r < 8; r++) {
                            float4 kv = ks4[(ty * 8 + r) * 17 + d4];
                            acc[r] = fmaf(p.x, kv.x, acc[r]);
                            acc[r] = fmaf(p.y, kv.y, acc[r]);
                            acc[r] = fmaf(p.z, kv.z, acc[r]);
                            acc[r] = fmaf(p.w, kv.w, acc[r]);
                        }
                    }
                }
#pragma unroll
                for (int r = 0; r < 8; r++) {
                    int row = ty * 8 + r;
                    float val = 0.f;
                    if (m < MDIM) {
                        float dash = NORMALIZER * acc[r];
                        val = c1 * (__expf(dash - diag[row] - stab) + KEPS);
                    }
                    kp[row * MPAD + m] = val;
                }
            }
        }
        __syncthreads();

        // phase 2: Cl[m][e] += sum_r kp[r][m] * vs[r][e]   (4m x 4e per tile)
        for (int t = tid; t < 17 * 68; t += 256) {
            int eg = t / 68, mg = t - eg * 68;
            float4 a0 = Cl4[(mg * 4 + 0) * 17 + eg];
            float4 a1 = Cl4[(mg * 4 + 1) * 17 + eg];
            float4 a2 = Cl4[(mg * 4 + 2) * 17 + eg];
            float4 a3 = Cl4[(mg * 4 + 3) * 17 + eg];
#pragma unroll 4
            for (int r = 0; r < 32; r++) {
                float4 kq = kp4[r * 68 + mg];
                float4 vq = vs4[r * 17 + eg];
                a0.x = fmaf(kq.x, vq.x, a0.x); a0.y = fmaf(kq.x, vq.y, a0.y);
                a0.z = fmaf(kq.x, vq.z, a0.z); a0.w = fmaf(kq.x, vq.w, a0.w);
                a1.x = fmaf(kq.y, vq.x, a1.x); a1.y = fmaf(kq.y, vq.y, a1.y);
                a1.z = fmaf(kq.y, vq.z, a1.z); a1.w = fmaf(kq.y, vq.w, a1.w);
                a2.x = fmaf(kq.z, vq.x, a2.x); a2.y = fmaf(kq.z, vq.y, a2.y);
                a2.z = fmaf(kq.z, vq.z, a2.z); a2.w = fmaf(kq.z, vq.w, a2.w);
                a3.x = fmaf(kq.w, vq.x, a3.x); a3.y = fmaf(kq.w, vq.y, a3.y);
                a3.z = fmaf(kq.w, vq.z, a3.z); a3.w = fmaf(kq.w, vq.w, a3.w);
            }
            Cl4[(mg * 4 + 0) * 17 + eg] = a0;
            Cl4[(mg * 4 + 1) * 17 + eg] = a1;
            Cl4[(mg * 4 + 2) * 17 + eg] = a2;
            Cl4[(mg * 4 + 3) * 17 + eg] = a3;
        }
    }
    __syncthreads();
    // flush to global C
    float* gC = g_C + (size_t)bh * MDIM * ECOLS;
    for (int idx = tid; idx < MDIM * ECOLS; idx += 256) {
        int m = idx / ECOLS, e = idx - m * ECOLS;
        atomicAdd(&gC[idx], Cl[m * EPAD + e]);
    }
}

// =======================================================================
// Kernel C: qp (per-row stabilized) then out = D_inv * qp @ C
// grid: 32 bh * 32 chunks of 128 rows = 1024 blocks, 256 threads
// =======================================================================
__global__ void __launch_bounds__(256) out_kernel(const float* __restrict__ qq,
                                                  const float* __restrict__ proj,
                                                  float* __restrict__ out) {
    extern __shared__ float sm[];
    float* ps     = sm;                      // 18088
    float* Cs     = ps + MDIM * PSTR;        // [272][68] 18496
    float* qp     = Cs + MPAD * EPAD;        // 32*272 = 8704
    float* qs     = qp + 32 * MPAD;          // 2176
    float* diag   = qs + 32 * PSTR;          // 32
    float* stab_s = diag + 32;               // 32
    float* den    = stab_s + 32;             // 32

    int tid = threadIdx.x;
    load_proj(ps, proj, tid);

    int bh = blockIdx.x >> 5;
    int row0 = (blockIdx.x & 31) * 128;
    const float* gC = g_C + (size_t)bh * MDIM * ECOLS;
    for (int i = tid; i < MPAD * EPAD; i += 256) {
        int m = i / EPAD, e = i - m * EPAD;
        float v = 0.f;
        if (m < MDIM && e < ECOLS) v = gC[m * ECOLS + e];
        Cs[i] = v;
    }
    const float* qbase = qq + ((size_t)bh * NSEQ + row0) * DDIM;
    float* obase = out + ((size_t)bh * NSEQ + row0) * DDIM;

    int tx = tid & 63, ty = tid >> 6;
    const float4* ps4 = (const float4*)ps;
    const float4* qs4 = (const float4*)qs;
    const float4* Cs4 = (const float4*)Cs;

    for (int s = 0; s < 4; s++) {
        __syncthreads();
        load_tile64(qs, qbase + s * 32 * DDIM, tid);
        __syncthreads();
        if (tid < 32) {
            float ssum = 0.f;
#pragma unroll
            for (int d4 = 0; d4 < 16; d4++) {
                float4 kv2 = qs4[tid * 17 + d4];
                ssum += kv2.x * kv2.x + kv2.y * kv2.y + kv2.z * kv2.z + kv2.w * kv2.w;
            }
            diag[tid] = DIAGC * ssum;
        }
        __syncthreads();

        // phase 1: raw dash into qp (pads = -inf)
        for (int stripe = 0; stripe < 5; stripe++) {
            int m = stripe * 64 + tx;
            if (m < MPAD) {
                float acc[8];
#pragma unroll
                for (int r = 0; r < 8; r++) acc[r] = 0.f;
                if (m < MDIM) {
                    const float4* pm = ps4 + m * 17;
#pragma unroll
                    for (int d4 = 0; d4 < 16; d4++) {
                        float4 p = pm[d4];
#pragma unroll
                        for (int r = 0; r < 8; r++) {
                            float4 kv = qs4[(ty * 8 + r) * 17 + d4];
                            acc[r] = fmaf(p.x, kv.x, acc[r]);
                            acc[r] = fmaf(p.y, kv.y, acc[r]);
                            acc[r] = fmaf(p.z, kv.z, acc[r]);
                            acc[r] = fmaf(p.w, kv.w, acc[r]);
                        }
                    }
                }
#pragma unroll
                for (int r = 0; r < 8; r++) {
                    int row = ty * 8 + r;
                    qp[row * MPAD + m] = (m < MDIM) ? NORMALIZER * acc[r] : -INFINITY;
                }
            }
        }
        __syncthreads();

        // per-row max (8 threads per row)
        {
            int r = tid >> 3, part = tid & 7;
            float mv = -INFINITY;
#pragma unroll 4
            for (int m = part; m < MPAD; m += 8) mv = fmaxf(mv, qp[r * MPAD + m]);
            mv = fmaxf(mv, __shfl_xor_sync(0xffffffffu, mv, 1));
            mv = fmaxf(mv, __shfl_xor_sync(0xffffffffu, mv, 2));
            mv = fmaxf(mv, __shfl_xor_sync(0xffffffffu, mv, 4));
            if (part == 0) stab_s[r] = mv;
        }
        __syncthreads();

        // transform to qp
        for (int i = tid; i < 32 * MPAD; i += 256) {
            int r = i / MPAD, m = i - r * MPAD;
            float dv = qp[i];
            float val = 0.f;
            if (m < MDIM) val = RATIO * (__expf(dv - diag[r] - stab_s[r]) + KEPS);
            qp[i] = val;
        }
        __syncthreads();

        // denominator: den[r] = sum_m qp[r][m] * Cs[m][64]
        {
            int r = tid >> 3, part = tid & 7;
            float dd = 0.f;
#pragma unroll 4
            for (int m = part; m < MPAD; m += 8) dd += qp[r * MPAD + m] * Cs[m * EPAD + 64];
            dd += __shfl_xor_sync(0xffffffffu, dd, 1);
            dd += __shfl_xor_sync(0xffffffffu, dd, 2);
            dd += __shfl_xor_sync(0xffffffffu, dd, 4);
            if (part == 0) den[r] = dd;
        }
        __syncthreads();

        // out: 2 rows x 4 e-cols per thread, 256 threads cover 32x64 exactly
        {
            int rg = tid >> 4;          // 0..15 -> r0 = 2*rg
            int eg = tid & 15;          // e0 = 4*eg
            int r0 = rg * 2;
            float4 a0 = make_float4(0.f, 0.f, 0.f, 0.f);
            float4 a1 = make_float4(0.f, 0.f, 0.f, 0.f);
#pragma unroll 4
            for (int m = 0; m < MPAD; m++) {
                float q0 = qp[r0 * MPAD + m];
                float q1 = qp[(r0 + 1) * MPAD + m];
                float4 c = Cs4[m * 17 + eg];
                a0.x = fmaf(q0, c.x, a0.x); a0.y = fmaf(q0, c.y, a0.y);
                a0.z = fmaf(q0, c.z, a0.z); a0.w = fmaf(q0, c.w, a0.w);
                a1.x = fmaf(q1, c.x, a1.x); a1.y = fmaf(q1, c.y, a1.y);
                a1.z = fmaf(q1, c.z, a1.z); a1.w = fmaf(q1, c.w, a1.w);
            }
            float di0 = 1.0f / den[r0];
            float di1 = 1.0f / den[r0 + 1];
            float4* o0 = (float4*)(obase + (size_t)(s * 32 + r0) * DDIM);
            float4* o1 = (float4*)(obase + (size_t)(s * 32 + r0 + 1) * DDIM);
            o0[eg] = make_float4(a0.x * di0, a0.y * di0, a0.z * di0, a0.w * di0);
            o1[eg] = make_float4(a1.x * di1, a1.y * di1, a1.z * di1, a1.w * di1);
        }
        __syncthreads();
    }
}

// =======================================================================
extern "C" void kernel_launch(void* const* d_in, const int* in_sizes, int n_in,
                              void* d_out, int out_size) {
    // identify projection matrix by its unique size; q,k,v keep relative order
    int pidx = -1;
    for (int i = 0; i < n_in; i++) if (in_sizes[i] == MDIM * DDIM) pidx = i;
    const float* rest[3] = {nullptr, nullptr, nullptr};
    int rc = 0;
    for (int i = 0; i < n_in && rc < 3; i++) {
        if (i == pidx) continue;
        rest[rc++] = (const float*)d_in[i];
    }
    const float* q = rest[0];
    const float* k = rest[1];
    const float* v = rest[2];
    const float* proj = (const float*)d_in[pidx];
    float* out = (float*)d_out;

    int smA = (MDIM * PSTR + 32 * PSTR) * (int)sizeof(float);                       // ~81 KB
    int smB = (MDIM * PSTR + MPAD * EPAD + 32 * MPAD + 2 * 32 * PSTR + 32) * (int)sizeof(float);      // ~194 KB
    int smC = (MDIM * PSTR + MPAD * EPAD + 32 * MPAD + 32 * PSTR + 96) * (int)sizeof(float);          // ~186 KB

    cudaFuncSetAttribute(kmax_kernel,    cudaFuncAttributeMaxDynamicSharedMemorySize, smA);
    cudaFuncSetAttribute(context_kernel, cudaFuncAttributeMaxDynamicSharedMemorySize, smB);
    cudaFuncSetAttribute(out_kernel,     cudaFuncAttributeMaxDynamicSharedMemorySize, smC);

    init_kernel<<<512, 256>>>();
    kmax_kernel<<<BH * 32, 256, smA>>>(k, proj);
    context_kernel<<<BH * 8, 256, smB>>>(k, v, proj);
    out_kernel<<<BH * 32, 256, smC>>>(q, proj, out);
}